// round 10
// baseline (speedup 1.0000x reference)
#include <cuda_runtime.h>
#include <cuda_fp16.h>
#include <stdint.h>

// rgb[n,d] = (1/Z_n) * sum_e enc[n,e] * D[n, d*72+e]
// D = A @ W',  A[n,c] = exp2(s'_nc - ub_n),  s' = x[:3].(centroid*log2e),
// ub_n = |x[:3]| * max_c |centroid'_c|
// Pipelined: softmax/pack(t+1) overlaps GEMM(t).
// 16 warps = 2 m-groups (64 rows) x 4 k-quarters (64) x 2 n-halves.
// B fragment redundancy 2x (was 4x) -> ~halved crossbar traffic.

constexpr int TPB    = 512;
constexpr int TILE_M = 128;
constexpr int NC     = 256;
constexpr int EDIM   = 72;
constexpr int NOUT   = 216;

constexpr int ROW_B  = 528;            // A/W' smem row bytes (132 words)
constexpr int ENC_B  = 544;            // bytes per enc e-pair row
constexpr int ENC_BUF = 36 * ENC_B;    // 19584

constexpr int OFF_CENT = 0;                          // 4096
constexpr int OFF_MRED = 4096;                       // 64
constexpr int OFF_WP   = 4160;                       // 216*528 = 114048
constexpr int OFF_A    = OFF_WP + NOUT * ROW_B;      // 118208
constexpr int OFF_ENC  = OFF_A + TILE_M * ROW_B;     // 185792 (x2)
constexpr int OFF_INVZ = OFF_ENC + 2 * ENC_BUF;      // 224960 (2*128 floats)
constexpr int OFF_RACC = OFF_INVZ + 1024;            // 225984 (2*512 floats)
constexpr int SMEM_BYTES = OFF_RACC + 4096;          // 230080

constexpr float LOG2E = 1.4426950408889634f;

__device__ __forceinline__ uint32_t s2u(const void* p) {
    uint32_t a;
    asm("{ .reg .u64 t; cvta.to.shared.u64 t, %1; cvt.u32.u64 %0, t; }"
        : "=r"(a) : "l"(p));
    return a;
}
__device__ __forceinline__ void ldsm4(uint32_t* r, uint32_t addr) {
    asm volatile("ldmatrix.sync.aligned.m8n8.x4.shared.b16 {%0,%1,%2,%3}, [%4];"
                 : "=r"(r[0]), "=r"(r[1]), "=r"(r[2]), "=r"(r[3]) : "r"(addr));
}
__device__ __forceinline__ void ldsm2(uint32_t* r, uint32_t addr) {
    asm volatile("ldmatrix.sync.aligned.m8n8.x2.shared.b16 {%0,%1}, [%2];"
                 : "=r"(r[0]), "=r"(r[1]) : "r"(addr));
}
__device__ __forceinline__ void lds128(uint32_t& r0, uint32_t& r1,
                                       uint32_t& r2, uint32_t& r3, uint32_t addr) {
    asm volatile("ld.shared.v4.b32 {%0,%1,%2,%3}, [%4];"
                 : "=r"(r0), "=r"(r1), "=r"(r2), "=r"(r3) : "r"(addr));
}
__device__ __forceinline__ void hmma(float& d0, float& d1, float& d2, float& d3,
                                     const uint32_t* a, const uint32_t* b) {
    asm volatile("mma.sync.aligned.m16n8k16.row.col.f32.f16.f16.f32 "
                 "{%0,%1,%2,%3}, {%4,%5,%6,%7}, {%8,%9}, {%0,%1,%2,%3};"
                 : "+f"(d0), "+f"(d1), "+f"(d2), "+f"(d3)
                 : "r"(a[0]), "r"(a[1]), "r"(a[2]), "r"(a[3]), "r"(b[0]), "r"(b[1]));
}
__device__ __forceinline__ void fold2(float& acc, float d0, float d1, uint32_t h2raw) {
    __half2 h = *reinterpret_cast<__half2*>(&h2raw);
    float2 e = __half22float2(h);
    acc = fmaf(d0, e.x, fmaf(d1, e.y, acc));
}

// One 8-col strip: 4 ldsm2 B frags (k-quarter = 4 ksteps), 16 HMMAs (4 chains),
// 2 bulk LDS.128 enc folds covering the warp's 8 row-groups.
template<int SL>
__device__ __forceinline__ void gemm_strip(
    uint32_t bstrip, const uint32_t (&a)[4][4][4], int eo,
    uint32_t eb, float (&acc)[8][2])
{
    uint32_t b[4][2];
#pragma unroll
    for (int kk = 0; kk < 4; ++kk) ldsm2(b[kk], bstrip + kk * 32);

    float d[4][4];
#pragma unroll
    for (int mt = 0; mt < 4; ++mt)
#pragma unroll
        for (int i = 0; i < 4; ++i) d[mt][i] = 0.f;

#pragma unroll
    for (int kk = 0; kk < 4; ++kk)
#pragma unroll
        for (int mt = 0; mt < 4; ++mt)
            hmma(d[mt][0], d[mt][1], d[mt][2], d[mt][3], a[mt][kk], b[kk]);

    const uint32_t ea = eb + (uint32_t)(eo >> 1) * ENC_B;
    uint32_t r0, r1, r2, r3;
    lds128(r0, r1, r2, r3, ea);            // rows r, r+8, r+16, r+24
    fold2(acc[0][SL], d[0][0], d[0][1], r0);
    fold2(acc[1][SL], d[0][2], d[0][3], r1);
    fold2(acc[2][SL], d[1][0], d[1][1], r2);
    fold2(acc[3][SL], d[1][2], d[1][3], r3);
    lds128(r0, r1, r2, r3, ea + 128);      // rows r+32 .. r+56
    fold2(acc[4][SL], d[2][0], d[2][1], r0);
    fold2(acc[5][SL], d[2][2], d[2][3], r1);
    fold2(acc[6][SL], d[3][0], d[3][1], r2);
    fold2(acc[7][SL], d[3][2], d[3][3], r3);
}

__device__ __forceinline__ void load_afrags(uint32_t (&a)[4][4][4],
                                            uint32_t sb, int mw, int kh, int l)
{
    const uint32_t a_base = sb + OFF_A
        + (uint32_t)((mw * 64 + (l & 15)) * ROW_B + kh * 128 + (l >> 4) * 16);
#pragma unroll
    for (int mt = 0; mt < 4; ++mt)
#pragma unroll
        for (int kk = 0; kk < 4; ++kk)
            ldsm4(a[mt][kk], a_base + mt * 16 * ROW_B + kk * 32);
}

// Register-lean softmax + enc + A-pack (4 lane-adjacent threads per point).
__device__ __forceinline__ void softmax_pack(
    const float* __restrict__ X, const float4* __restrict__ c4,
    __half2* __restrict__ atp, __half2* __restrict__ encp,
    float* __restrict__ invZp, float Mn,
    int t, int N, int pt, int q, int gp)
{
    const int p = t * TILE_M + pt;
    float x0 = 0.f, x1 = 0.f, x2 = 0.f;
    if (p < N) { x0 = X[p * 6 + 0]; x1 = X[p * 6 + 1]; x2 = X[p * 6 + 2]; }

    if (q < 3) {
#pragma unroll
        for (int dd = 0; dd < 2; ++dd) {
            const int d = 2 * q + dd;
            float xv = (p < N) ? X[p * 6 + d] : 0.f;
            float sv[6], cv[6], s, c;
            __sincosf(xv, &s, &c);
#pragma unroll
            for (int k = 0; k < 6; ++k) {
                sv[k] = s; cv[k] = c;
                float s2 = 2.f * s * c;
                float c2 = fmaf(-2.f * s, s, 1.f);
                s = s2; c = c2;
            }
#pragma unroll
            for (int tt = 0; tt < 3; ++tt) {
                encp[(d * 6 + tt) * (ENC_B / 4) + gp]     = __floats2half2_rn(sv[2 * tt], sv[2 * tt + 1]);
                encp[(d * 6 + 3 + tt) * (ENC_B / 4) + gp] = __floats2half2_rn(cv[2 * tt], cv[2 * tt + 1]);
            }
        }
    }

    const float ub = sqrtf(fmaf(x0, x0, fmaf(x1, x1, x2 * x2))) * Mn;
    const float4* cb = c4 + (q << 6);
    float z = 0.f;
#pragma unroll 4
    for (int j = 0; j < 64; j += 2) {
        const int u0 = (j + 2 * q) & 63;
        float4 ca = cb[u0], cd = cb[u0 + 1];
        float s0 = fmaf(x0, ca.x, fmaf(x1, ca.y, x2 * ca.z)) - ub;
        float s1 = fmaf(x0, cd.x, fmaf(x1, cd.y, x2 * cd.z)) - ub;
        float w0, w1;
        asm("ex2.approx.ftz.f32 %0, %1;" : "=f"(w0) : "f"(s0));
        asm("ex2.approx.ftz.f32 %0, %1;" : "=f"(w1) : "f"(s1));
        __half2 h2 = __floats2half2_rn(w0, w1);
        z += __low2float(h2) + __high2float(h2);
        atp[pt * 132 + (((q << 6) + u0) >> 1)] = h2;
    }
    z += __shfl_xor_sync(0xffffffffu, z, 1);
    z += __shfl_xor_sync(0xffffffffu, z, 2);
    if (q == 0) invZp[pt] = __frcp_rn(z);
}

__global__ __launch_bounds__(TPB, 1)
void rgb_hmma_kernel(const float* __restrict__ X,
                     const float* __restrict__ W,
                     const float* __restrict__ cent,
                     float* __restrict__ out, int N, int n_tiles)
{
    extern __shared__ char smem[];
    const uint32_t sb = s2u(smem);
    float4*  c4   = reinterpret_cast<float4*>(smem + OFF_CENT);
    float*   mred = reinterpret_cast<float*>(smem + OFF_MRED);
    __half*  wp   = reinterpret_cast<__half*>(smem + OFF_WP);
    __half2* atp  = reinterpret_cast<__half2*>(smem + OFF_A);
    float*   invZ = reinterpret_cast<float*>(smem + OFF_INVZ);
    float*   racc = reinterpret_cast<float*>(smem + OFF_RACC);

    const int tid = threadIdx.x;
    const int w = tid >> 5, l = tid & 31;

    for (int i = tid; i < NC; i += TPB) {
        float4 qv;
        qv.x = cent[i * 3 + 0] * LOG2E;
        qv.y = cent[i * 3 + 1] * LOG2E;
        qv.z = cent[i * 3 + 2] * LOG2E;
        qv.w = 0.f;
        c4[i] = qv;
    }
    for (int i = tid; i < 768 * EDIM; i += TPB) {
        int r = i / EDIM, e = i - r * EDIM;
        int c = r / 3, d = r - 3 * c;
        wp[(d * EDIM + e) * (ROW_B / 2) + c] = __float2half_rn(W[i]);
    }
    racc[tid] = 0.f;
    racc[tid + 512] = 0.f;
    __syncthreads();

    float mn2 = 0.f;
    if (tid < NC) {
        float4 cc = c4[tid];
        mn2 = fmaf(cc.x, cc.x, fmaf(cc.y, cc.y, cc.z * cc.z));
    }
#pragma unroll
    for (int o = 16; o > 0; o >>= 1)
        mn2 = fmaxf(mn2, __shfl_xor_sync(0xffffffffu, mn2, o));
    if (l == 0) mred[w] = mn2;
    __syncthreads();
    float M2 = mred[0];
#pragma unroll
    for (int i = 1; i < 16; ++i) M2 = fmaxf(M2, mred[i]);
    const float Mn = sqrtf(M2);

    const int pt = tid >> 2;
    const int q  = tid & 3;
    const int gp = (pt >> 5) * 32 + (pt & 7) * 4 + ((pt >> 3) & 3);
    const int mw = w & 1, kh = (w >> 1) & 3, nh = w >> 3;
    const int lq = l >> 2;
    const int G = gridDim.x;

    // B strip base: row (l&7), 16B chunk ((l>>3)&1), k-quarter kh
    const uint32_t bl2 = sb + OFF_WP
        + (uint32_t)((l & 7) * ROW_B + ((l >> 3) & 1) * 16 + kh * 128);
    // enc fold base: e-shift (l&3), warp row-block mw*64, sub-row lq
    const uint32_t eb0 = sb + OFF_ENC
        + (uint32_t)((l & 3) * ENC_B + mw * 256 + lq * 16);

    int t = blockIdx.x;
    int par = 0;
    uint32_t a[4][4][4];
    if (t < n_tiles)
        softmax_pack(X, c4, atp,
                     reinterpret_cast<__half2*>(smem + OFF_ENC),
                     invZ, Mn, t, N, pt, q, gp);
    __syncthreads();
    if (t < n_tiles) load_afrags(a, sb, mw, kh, l);
    __syncthreads();

    for (; t < n_tiles; t += G) {
        const int tn = t + G;
        const int parn = par ^ 1;

        if (tn < n_tiles)
            softmax_pack(X, c4, atp,
                         reinterpret_cast<__half2*>(smem + OFF_ENC + parn * ENC_BUF),
                         invZ + parn * TILE_M, Mn, tn, N, pt, q, gp);

        const uint32_t eb = eb0 + (uint32_t)par * ENC_BUF;
        float acc[8][2];
#pragma unroll
        for (int g = 0; g < 8; ++g) { acc[g][0] = 0.f; acc[g][1] = 0.f; }

        if (nh == 0) {   // strips 0..13 : dch0 = s0..8 (SL0), dch1 = s9..13 (SL1)
#pragma unroll
            for (int s = 0; s < 9; ++s)
                gemm_strip<0>(bl2 + (uint32_t)(s * 8 * ROW_B), a, s * 8, eb, acc);
#pragma unroll
            for (int s = 9; s < 14; ++s)
                gemm_strip<1>(bl2 + (uint32_t)(s * 8 * ROW_B), a, s * 8 - 72, eb, acc);
        } else {         // strips 14..17 : dch1 (SL0), 18..26 : dch2 (SL1)
#pragma unroll
            for (int s = 14; s < 18; ++s)
                gemm_strip<0>(bl2 + (uint32_t)(s * 8 * ROW_B), a, s * 8 - 72, eb, acc);
#pragma unroll
            for (int s = 18; s < 27; ++s)
                gemm_strip<1>(bl2 + (uint32_t)(s * 8 * ROW_B), a, s * 8 - 144, eb, acc);
        }

        // quad-reduce + atomic into racc[par]: row = mw*64 + g*8 + lq, col = nh+sl
        float* raccp = racc + par * 512;
#pragma unroll
        for (int g = 0; g < 8; ++g)
#pragma unroll
            for (int sl = 0; sl < 2; ++sl) {
                float v = acc[g][sl];
                v += __shfl_xor_sync(0xffffffffu, v, 1);
                v += __shfl_xor_sync(0xffffffffu, v, 2);
                if ((l & 3) == 0)
                    atomicAdd(&raccp[(mw * 64 + g * 8 + lq) * 4 + nh + sl], v);
            }
        __syncthreads();   // sync1: pack(t+1) & atomics(t) complete

        if (tn < n_tiles) load_afrags(a, sb, mw, kh, l);

        if (tid < TILE_M) {
            float* rp = racc + par * 512 + tid * 4;
            const int po2 = t * TILE_M + tid;
            if (po2 < N) {
                const float iz = invZ[par * TILE_M + tid];
                out[po2 * 3 + 0] = rp[0] * iz;
                out[po2 * 3 + 1] = rp[1] * iz;
                out[po2 * 3 + 2] = rp[2] * iz;
            }
            rp[0] = 0.f; rp[1] = 0.f; rp[2] = 0.f; rp[3] = 0.f;
        }
        __syncthreads();   // sync2: a-frags(t+1) loaded, racc recycled

        par = parn;
    }
}

extern "C" void kernel_launch(void* const* d_in, const int* in_sizes, int n_in,
                              void* d_out, int out_size)
{
    const float* X    = (const float*)d_in[0];  // [N, 6]
    const float* W    = (const float*)d_in[1];  // [768, 72]
    const float* cent = (const float*)d_in[2];  // [256, 3]
    float* out = (float*)d_out;                 // [N, 3]

    const int N = in_sizes[0] / 6;
    const int n_tiles = (N + TILE_M - 1) / TILE_M;

    int dev = 0, sms = 148;
    cudaGetDevice(&dev);
    cudaDeviceGetAttribute(&sms, cudaDevAttrMultiProcessorCount, dev);

    cudaFuncSetAttribute(rgb_hmma_kernel,
                         cudaFuncAttributeMaxDynamicSharedMemorySize, SMEM_BYTES);

    const int grid = n_tiles < sms ? n_tiles : sms;
    rgb_hmma_kernel<<<grid, TPB, SMEM_BYTES>>>(X, W, cent, out, N, n_tiles);
}